// round 15
// baseline (speedup 1.0000x reference)
#include <cuda_runtime.h>

#define NSTEP 51200
#define BATCH 512
// LSTM chunking
#define CHL   16
#define LEADL 96
#define NCHL  (NSTEP / CHL)
// HR-module chunking (fused kernel)
#define CHK   128          // kept steps per block
#define NCHK  (NSTEP / CHK)
#define RMAX  (CHK + 64)   // 32 lif3 lead + 32 lif4 lead

// ---------------- scratch (static device arrays; no allocation) ----------------
__device__ float g_xproj[NSTEP * 40];
__device__ float g_hseq [NSTEP * 10];
__device__ float g_out1 [NSTEP * 20];
__device__ float g_out2 [NSTEP * 10];
__device__ float g_sfin [NSTEP * 10];
__device__ float g_fused[BATCH * 200];
__device__ float g_part [BATCH * 2];
__device__ float g_stats[3];

__device__ __forceinline__ float sigf(float x)  { return __fdividef(1.f, 1.f + __expf(-x)); }
__device__ __forceinline__ float tfast(float x) { return __fdividef(2.f, 1.f + __expf(-2.f * x)) - 1.f; }

// packed f32x2 helpers (Blackwell FFMA2; IEEE-exact per component)
__device__ __forceinline__ unsigned long long pk2(float a, float b) {
    unsigned long long r; asm("mov.b64 %0, {%1, %2};" : "=l"(r) : "f"(a), "f"(b)); return r;
}
__device__ __forceinline__ unsigned long long fma2(unsigned long long a, unsigned long long b,
                                                   unsigned long long c) {
    unsigned long long d;
    asm("fma.rn.f32x2 %0, %1, %2, %3;" : "=l"(d) : "l"(a), "l"(b), "l"(c)); return d;
}
__device__ __forceinline__ void upk2(unsigned long long v, float& lo, float& hi) {
    asm("mov.b64 {%0, %1}, %2;" : "=f"(lo), "=f"(hi) : "l"(v));
}

// ---------------- K1: LSTM input projection (fully parallel) ----------------
__global__ void k_xproj(const float* __restrict__ x, const float* __restrict__ wih,
                        const float* __restrict__ bih, const float* __restrict__ bhh) {
    __shared__ float xs[64 * 100];
    __shared__ float ws[40 * 65];
    __shared__ float bs[40];
    int b = blockIdx.x, tid = threadIdx.x;
    const float* xg = x + b * 6400;
    for (int i = tid; i < 6400; i += 256) xs[i] = xg[i];
    for (int i = tid; i < 2560; i += 256) ws[(i >> 6) * 65 + (i & 63)] = wih[i];
    if (tid < 40) bs[tid] = bih[tid] + bhh[tid];
    __syncthreads();
    for (int i = tid; i < 4000; i += 256) {
        int tp = i / 40, j = i % 40;
        float acc = bs[j];
        #pragma unroll
        for (int c0 = 0; c0 < 64; c0++)
            acc = fmaf(xs[c0 * 100 + tp], ws[j * 65 + c0], acc);
        g_xproj[(b * 100 + tp) * 40 + j] = acc;
    }
}

// ---------------- K2: LSTM scan, chunked, FFMA2-packed gate dot-products ----------
__global__ void k_lstm(const float* __restrict__ whh) {
    const int lane = threadIdx.x;
    const int k = lane < 10 ? lane : 0;
    unsigned long long wif[10], wgo[10];
    #pragma unroll
    for (int m = 0; m < 10; m++) {
        wif[m] = pk2(whh[k * 10 + m],        whh[(k + 10) * 10 + m]);
        wgo[m] = pk2(whh[(k + 20) * 10 + m], whh[(k + 30) * 10 + m]);
    }
    const int t1 = blockIdx.x * CHL;
    const int t2 = t1 + CHL;
    int t0 = t1 - LEADL; if (t0 < 0) t0 = 0;

    unsigned long long hh[10];
    #pragma unroll
    for (int m = 0; m < 10; m++) hh[m] = 0ull;
    float c = 0.f;
    const float* xp = g_xproj;
    float A[4], B[4];

#define LOAD4(S, t) { const float* p = xp + (size_t)(t) * 40 + k; \
    S[0] = p[0]; S[1] = p[10]; S[2] = p[20]; S[3] = p[30]; }

#define STEP(S, tc) { int tp = (tc) + 2; if (tp > NSTEP - 1) tp = NSTEP - 1; \
    unsigned long long aif = pk2(S[0], S[1]), ago = pk2(S[2], S[3]); \
    LOAD4(S, tp); \
    _Pragma("unroll") \
    for (int m = 0; m < 10; m++) { \
        aif = fma2(wif[m], hh[m], aif); ago = fma2(wgo[m], hh[m], ago); } \
    float ai, af, ag, ao; upk2(aif, ai, af); upk2(ago, ag, ao); \
    float tg = tfast(ag); \
    c = fmaf(sigf(af), c, sigf(ai) * tg); \
    float hk = sigf(ao) * tfast(c); \
    if (lane < 10 && (tc) >= t1) g_hseq[(size_t)(tc) * 10 + lane] = hk; \
    _Pragma("unroll") \
    for (int m = 0; m < 10; m++) { \
        float hm = __shfl_sync(0xffffffffu, hk, m); hh[m] = pk2(hm, hm); } }

    LOAD4(A, t0); LOAD4(B, t0 + 1);
    for (int t = t0; t < t2; t += 2) {
        STEP(A, t);
        STEP(B, t + 1);
    }
#undef STEP
#undef LOAD4
}

// ---------------- fc+skip inner body ----------------
template <int FOUT>
__device__ __forceinline__ void fcskip_row(const float* __restrict__ s4row,
                                           const float* __restrict__ xrow,
                                           const float* __restrict__ wfc,
                                           const float* __restrict__ wsk,
                                           const float* __restrict__ bb,
                                           float* __restrict__ orow) {
    float acc[FOUT];
    #pragma unroll
    for (int o = 0; o < FOUT; o++) acc[o] = bb[o];
    #pragma unroll
    for (int m = 0; m < 20; m++) {
        float sm = s4row[m], xm = xrow[m];
        #pragma unroll
        for (int o = 0; o < FOUT; o++)
            acc[o] = fmaf(sm, wfc[o * 20 + m], fmaf(xm, wsk[o * 20 + m], acc[o]));
    }
    #pragma unroll
    for (int o = 0; o < FOUT; o++) orow[o] = acc[o];
}

// ---------------- K3: fused HR module (templated; segmented in-block LIF chains;
//                   lif4 writes to a SEPARATE buffer -> no cross-segment race) ----
template <int WHICH>
__global__ void __launch_bounds__(256, 2)
k_hr(const float* __restrict__ scw, const float* __restrict__ scb,
     const float* __restrict__ cw,  const float* __restrict__ cb,
     const float* __restrict__ fw,  const float* __restrict__ fb,
     const float* __restrict__ skw, const float* __restrict__ skb) {
    extern __shared__ float sm[];
    float* sx  = sm;                 // [RMAX][20] xin
    float* shl = sm + RMAX * 20;     // [RMAX][60] lif3 spikes
    float* sc4 = sm + RMAX * 80;     // [RMAX][20] staging / conv out
    float* ss4 = sm + RMAX * 100;    // [RMAX][20] lif4 spikes (separate: race-free)

    constexpr int FOUT = WHICH ? 10 : 20;
    __shared__ float w_cv[1200], w_fc[FOUT * 20], w_sk[FOUT * 20], w_sc[200];
    __shared__ float b_cv[20], b_fs[FOUT], b_sc[20];

    const int tid = threadIdx.x;
    for (int i = tid; i < 1200; i += 256) w_cv[i] = cw[i];
    for (int i = tid; i < FOUT * 20; i += 256) { w_fc[i] = fw[i]; w_sk[i] = skw[i]; }
    if (WHICH == 0) for (int i = tid; i < 200; i += 256) w_sc[i] = scw[i];
    if (tid < 20) { b_cv[tid] = cb[tid]; if (WHICH == 0) b_sc[tid] = scb[tid]; }
    if (tid < FOUT) b_fs[tid] = fb[tid] + skb[tid];

    const int t1 = blockIdx.x * CHK;
    int t0 = t1 - 64; if (t0 < 0) t0 = 0;
    const int R = t1 + CHK - t0;
    const int rconv = (t1 >= 32 ? t1 - 32 : 0) - t0;   // 32 (or 0 for block 0)
    const int rkeep = t1 - t0;                         // 64 (or 0 for block 0)

    // ---- stage A: xin into sx ----
    if (WHICH == 0) {
        // stage hseq chunk into sc4 (coalesced float4), then small matmul from smem
        {
            const float4* h4 = (const float4*)(g_hseq + (size_t)t0 * 10);
            float4* d4 = (float4*)sc4;
            const int n4 = (R * 10) >> 2;
            for (int i = tid; i < n4; i += 256) d4[i] = h4[i];
        }
        __syncthreads();
        for (int i = tid; i < R * 20; i += 256) {
            int r = i / 20, o = i % 20;
            float acc = b_sc[o];
            const float* hr = sc4 + r * 10;
            #pragma unroll
            for (int m = 0; m < 10; m++) acc = fmaf(hr[m], w_sc[o * 10 + m], acc);
            sx[i] = acc;
        }
    } else {
        const float4* s4p = (const float4*)(g_out1 + (size_t)t0 * 20);
        float4* d4 = (float4*)sx;
        const int n4 = (R * 20) >> 2;
        for (int i = tid; i < n4; i += 256) d4[i] = s4p[i];
    }
    __syncthreads();

    // ---- stage B: lif3, 4 time-segments x 60 chains (240 threads, depth <= 72) ----
    // reads sx (never written here), writes shl -> no cross-segment hazard.
    if (tid < 240) {
        const int seg = tid / 60;
        const int l = tid % 60;
        const int kk = l / 20, f = l % 20;
        float tau = (kk == 0) ? 1.2231301601484298f
                  : (kk == 1) ? 1.3678794411714423f : 1.4493289641172216f;
        float th  = (kk == 0) ? 0.14f : (kk == 1) ? 0.08f : 0.06f;
        float invt = 1.0f / tau, om = 1.0f - invt;
        const int OW = R - rconv;            // 160 (block 0: 128), divisible by 4
        const int ws = OW >> 2;              // 40 (block 0: 32)
        const int k1 = rconv + seg * ws;
        const int k2 = k1 + ws;
        int cs = k1 - 32; if (cs < 0) cs = 0;
        float v = 0.f;
        float* op = shl + f * 3 + kk;
        const float* ip = sx + f;
        #pragma unroll 2
        for (int r = cs; r < k2; r++) {
            float d = fmaf(v, om, fmaf(ip[r * 20], invt, -th));
            int msk = __float_as_int(d) >> 31;
            if (r >= k1) op[r * 60] = __int_as_float(~msk & 0x3f800000);
            v = __int_as_float(__float_as_int(d + th) & msk);
        }
    }
    __syncthreads();

    // ---- stage C: conv (rows [rconv,R)); warp-uniform output half (wv broadcast) ----
    {
        const int nrows = R - rconv;          // 160, or 128 for block 0 (mult of 32)
        const int ntask = nrows * 2;
        for (int task = tid; task < ntask; task += 256) {
            int r, ob;
            if (task < nrows) { r = rconv + task;         ob = 0;  }
            else              { r = rconv + task - nrows; ob = 10; }
            float acc[10];
            #pragma unroll
            for (int o = 0; o < 10; o++) acc[o] = b_cv[ob + o];
            const float4* hrow = (const float4*)(shl + r * 60);
            #pragma unroll
            for (int mb = 0; mb < 15; mb++) {
                float4 hv = hrow[mb];
                #pragma unroll
                for (int o = 0; o < 10; o++) {
                    const float4 wv = *(const float4*)(w_cv + (ob + o) * 60 + mb * 4);
                    acc[o] = fmaf(hv.x, wv.x, acc[o]);
                    acc[o] = fmaf(hv.y, wv.y, acc[o]);
                    acc[o] = fmaf(hv.z, wv.z, acc[o]);
                    acc[o] = fmaf(hv.w, wv.w, acc[o]);
                }
            }
            #pragma unroll
            for (int o = 0; o < 10; o++) sc4[r * 20 + ob + o] = acc[o];
        }
    }
    __syncthreads();

    // ---- stage D: lif4, 4 time-segments x 20 chains (80 threads, depth <= 64) ----
    // reads sc4 (conv out, never written here), writes ss4 -> race-free.
    if (tid < 80) {
        const int seg = tid / 20;
        const int f = tid % 20;
        const float invt = 1.0f / 1.3678794411714423f;
        const float om = 1.0f - invt, th = 0.08f;
        const int OW = R - rkeep;            // 128 always, divisible by 4
        const int ws = OW >> 2;              // 32
        const int k1 = rkeep + seg * ws;
        const int k2 = k1 + ws;
        int cs = k1 - 32; if (cs < rconv) cs = rconv;
        float v = 0.f;
        const float* ip = sc4 + f;
        float* op = ss4 + f;
        #pragma unroll 2
        for (int r = cs; r < k2; r++) {
            float d = fmaf(v, om, fmaf(ip[r * 20], invt, -th));
            int msk = __float_as_int(d) >> 31;
            if (r >= k1) op[r * 20] = __int_as_float(~msk & 0x3f800000);
            v = __int_as_float(__float_as_int(d + th) & msk);
        }
    }
    __syncthreads();

    // ---- stage E: fc + skip on keep rows ----
    {
        int r = rkeep + tid;
        if (r < R) {
            if (WHICH == 0)
                fcskip_row<20>(ss4 + r * 20, sx + r * 20, w_fc, w_sk, b_fs,
                               g_out1 + (size_t)(t0 + r) * 20);
            else
                fcskip_row<10>(ss4 + r * 20, sx + r * 20, w_fc, w_sk, b_fs,
                               g_out2 + (size_t)(t0 + r) * 10);
        }
    }
}

// ---------------- K4: final LIF over batch axis, chunked + 16-deep prefetch ring ----
__global__ void k_liff() {
    int idx = threadIdx.x;
    if (idx >= 1000) return;
    const float invt = 1.0f / 1.3678794411714423f;
    const float om = 1.0f - invt, th = 0.08f;
    const int b1 = blockIdx.x * 32, b2 = b1 + 32;
    int b0 = b1 - 48; if (b0 < 0) b0 = 0;
    const int n = b2 - b0;                 // 80, or 32 for block 0 (both mult of 16)
    const int wskip = b1 - b0;
    const float* ip = g_out2 + (size_t)b0 * 1000 + idx;
    float* op = g_sfin + (size_t)b0 * 1000 + idx;

    float v = 0.f;
    float xr[16];
    #pragma unroll
    for (int u = 0; u < 16; u++) xr[u] = fmaf(ip[(size_t)u * 1000], invt, -th);
    for (int bb = 0; bb < n; bb += 16) {
        #pragma unroll
        for (int u = 0; u < 16; u++) {
            int t = bb + u;
            float d = fmaf(v, om, xr[u]);
            int np = t + 16;
            float nx = (np < n) ? ip[(size_t)np * 1000] : 0.f;
            xr[u] = fmaf(nx, invt, -th);
            int msk = __float_as_int(d) >> 31;
            if (t >= wskip) op[(size_t)t * 1000] = __int_as_float(~msk & 0x3f800000);
            v = __int_as_float(__float_as_int(d + th) & msk);
        }
    }
}

// ---------------- K5: dp / avg / fused + per-batch partial sums ----------------
__global__ void k_fused() {
    int b = blockIdx.x, m = threadIdx.x;
    float dp[10];
    float s1 = 0.f, s2 = 0.f;
    if (m < 20) {
        const float* sb = g_sfin + b * 1000;
        float avgm = 0.f;
        #pragma unroll
        for (int j = 0; j < 10; j++) {
            float a = sb[(5 * m + 3) * 10 + j] + sb[(5 * m + 4) * 10 + j]
                    - sb[(5 * m + 0) * 10 + j] - sb[(5 * m + 1) * 10 + j];
            dp[j] = 0.5f * a;
            avgm += dp[j];
        }
        avgm *= 0.1f;
        #pragma unroll
        for (int j = 0; j < 10; j++) {
            float fv = dp[j] * avgm;
            g_fused[b * 200 + j * 20 + m] = fv;
            s1 += fv; s2 += fv * fv;
        }
    }
    #pragma unroll
    for (int off = 16; off; off >>= 1) {
        s1 += __shfl_xor_sync(0xffffffffu, s1, off);
        s2 += __shfl_xor_sync(0xffffffffu, s2, off);
    }
    if (m == 0) { g_part[b * 2] = s1; g_part[b * 2 + 1] = s2; }
}

// ---------------- K6: global mean/var ----------------
__global__ void k_stats(const float* __restrict__ gamma, const float* __restrict__ beta) {
    int l = threadIdx.x;
    float s1 = 0.f, s2 = 0.f;
    for (int i = l; i < BATCH; i += 32) { s1 += g_part[2 * i]; s2 += g_part[2 * i + 1]; }
    #pragma unroll
    for (int off = 16; off; off >>= 1) {
        s1 += __shfl_xor_sync(0xffffffffu, s1, off);
        s2 += __shfl_xor_sync(0xffffffffu, s2, off);
    }
    if (l == 0) {
        float n = (float)(BATCH * 200);
        float mean = s1 / n;
        float var = s2 / n - mean * mean;
        float rstd = 1.f / sqrtf(var + 1e-5f);
        g_stats[0] = mean; g_stats[1] = rstd * gamma[0]; g_stats[2] = beta[0];
    }
}

// ---------------- K7: BN + classifier + log_softmax ----------------
__global__ void k_logits(const float* __restrict__ clsw, const float* __restrict__ clsb,
                         float* __restrict__ out) {
    int b = blockIdx.x, l = threadIdx.x;
    float mean = g_stats[0], ga = g_stats[1], be = g_stats[2];
    float a0 = 0.f, a1 = 0.f, a2 = 0.f;
    for (int n = l; n < 200; n += 32) {
        float bn = (g_fused[b * 200 + n] - mean) * ga + be;
        a0 = fmaf(bn, clsw[n], a0);
        a1 = fmaf(bn, clsw[200 + n], a1);
        a2 = fmaf(bn, clsw[400 + n], a2);
    }
    #pragma unroll
    for (int off = 16; off; off >>= 1) {
        a0 += __shfl_xor_sync(0xffffffffu, a0, off);
        a1 += __shfl_xor_sync(0xffffffffu, a1, off);
        a2 += __shfl_xor_sync(0xffffffffu, a2, off);
    }
    if (l == 0) {
        float l0 = a0 + clsb[0], l1 = a1 + clsb[1], l2 = a2 + clsb[2];
        float mx = fmaxf(l0, fmaxf(l1, l2));
        float e0 = expf(l0 - mx), e1 = expf(l1 - mx), e2 = expf(l2 - mx);
        float lse = logf(e0 + e1 + e2) + mx;
        out[b * 3 + 0] = l0 - lse;
        out[b * 3 + 1] = l1 - lse;
        out[b * 3 + 2] = l2 - lse;
    }
}

// ---------------- launch ----------------
extern "C" void kernel_launch(void* const* d_in, const int* in_sizes, int n_in,
                              void* d_out, int out_size) {
    const float* x   = (const float*)d_in[0];
    const float* wih = (const float*)d_in[1];
    const float* whh = (const float*)d_in[2];
    const float* bih = (const float*)d_in[3];
    const float* bhh = (const float*)d_in[4];
    const float* scw = (const float*)d_in[5];
    const float* scb = (const float*)d_in[6];
    const float* c1w = (const float*)d_in[7];
    const float* c1b = (const float*)d_in[8];
    const float* f1w = (const float*)d_in[9];
    const float* f1b = (const float*)d_in[10];
    const float* s1w = (const float*)d_in[11];
    const float* s1b = (const float*)d_in[12];
    const float* c2w = (const float*)d_in[13];
    const float* c2b = (const float*)d_in[14];
    const float* f2w = (const float*)d_in[15];
    const float* f2b = (const float*)d_in[16];
    const float* s2w = (const float*)d_in[17];
    const float* s2b = (const float*)d_in[18];
    const float* gam = (const float*)d_in[19];
    const float* bet = (const float*)d_in[20];
    const float* clw = (const float*)d_in[21];
    const float* clb = (const float*)d_in[22];
    float* out = (float*)d_out;

    static int smem_set = 0;
    const int HR_SMEM = RMAX * 120 * sizeof(float);   // 92.2 KB
    if (!smem_set) {
        cudaFuncSetAttribute(k_hr<0>, cudaFuncAttributeMaxDynamicSharedMemorySize, HR_SMEM);
        cudaFuncSetAttribute(k_hr<1>, cudaFuncAttributeMaxDynamicSharedMemorySize, HR_SMEM);
        smem_set = 1;
    }

    k_xproj <<<512, 256>>>(x, wih, bih, bhh);
    k_lstm  <<<NCHL, 32>>>(whh);
    k_hr<0> <<<NCHK, 256, HR_SMEM>>>(scw, scb, c1w, c1b, f1w, f1b, s1w, s1b);
    k_hr<1> <<<NCHK, 256, HR_SMEM>>>(scw, scb, c2w, c2b, f2w, f2b, s2w, s2b);
    k_liff  <<<16, 1024>>>();
    k_fused <<<512, 32>>>();
    k_stats <<<1, 32>>>(gam, bet);
    k_logits<<<512, 32>>>(clw, clb, out);
}

// round 16
// speedup vs baseline: 1.8051x; 1.8051x over previous
#include <cuda_runtime.h>

#define NSTEP 51200
#define BATCH 512
// LSTM chunking
#define CHL   32
#define LEADL 96
#define NCHL  (NSTEP / CHL)
// HR-module chunking (fused kernel)
#define CHK   128          // kept steps per block
#define NCHK  (NSTEP / CHK)
#define RMAX  (CHK + 64)   // 32 lif3 lead + 32 lif4 lead

// ---------------- scratch (static device arrays; no allocation) ----------------
__device__ float g_xproj[NSTEP * 40];
__device__ float g_hseq [NSTEP * 10];
__device__ float g_out1 [NSTEP * 20];
__device__ float g_out2 [NSTEP * 10];
__device__ float g_sfin [NSTEP * 10];
__device__ float g_fused[BATCH * 200];
__device__ float g_part [BATCH * 2];
__device__ float g_stats[3];

__device__ __forceinline__ float sigf(float x)  { return __fdividef(1.f, 1.f + __expf(-x)); }
__device__ __forceinline__ float tfast(float x) { return __fdividef(2.f, 1.f + __expf(-2.f * x)) - 1.f; }

// packed f32x2 helpers (Blackwell FFMA2; IEEE-exact per component)
__device__ __forceinline__ unsigned long long pk2(float a, float b) {
    unsigned long long r; asm("mov.b64 %0, {%1, %2};" : "=l"(r) : "f"(a), "f"(b)); return r;
}
__device__ __forceinline__ unsigned long long fma2(unsigned long long a, unsigned long long b,
                                                   unsigned long long c) {
    unsigned long long d;
    asm("fma.rn.f32x2 %0, %1, %2, %3;" : "=l"(d) : "l"(a), "l"(b), "l"(c)); return d;
}
__device__ __forceinline__ void upk2(unsigned long long v, float& lo, float& hi) {
    asm("mov.b64 {%0, %1}, %2;" : "=f"(lo), "=f"(hi) : "l"(v));
}

// ---------------- K1: LSTM input projection (fully parallel) ----------------
__global__ void k_xproj(const float* __restrict__ x, const float* __restrict__ wih,
                        const float* __restrict__ bih, const float* __restrict__ bhh) {
    __shared__ float xs[64 * 100];
    __shared__ float ws[40 * 65];
    __shared__ float bs[40];
    int b = blockIdx.x, tid = threadIdx.x;
    const float* xg = x + b * 6400;
    for (int i = tid; i < 6400; i += 256) xs[i] = xg[i];
    for (int i = tid; i < 2560; i += 256) ws[(i >> 6) * 65 + (i & 63)] = wih[i];
    if (tid < 40) bs[tid] = bih[tid] + bhh[tid];
    __syncthreads();
    for (int i = tid; i < 4000; i += 256) {
        int tp = i / 40, j = i % 40;
        float acc = bs[j];
        #pragma unroll
        for (int c0 = 0; c0 < 64; c0++)
            acc = fmaf(xs[c0 * 100 + tp], ws[j * 65 + c0], acc);
        g_xproj[(b * 100 + tp) * 40 + j] = acc;
    }
}

// ---------------- K2: LSTM scan, chunked, FFMA2-packed gate dot-products ----------
__global__ void k_lstm(const float* __restrict__ whh) {
    const int lane = threadIdx.x;
    const int k = lane < 10 ? lane : 0;
    unsigned long long wif[10], wgo[10];
    #pragma unroll
    for (int m = 0; m < 10; m++) {
        wif[m] = pk2(whh[k * 10 + m],        whh[(k + 10) * 10 + m]);
        wgo[m] = pk2(whh[(k + 20) * 10 + m], whh[(k + 30) * 10 + m]);
    }
    const int t1 = blockIdx.x * CHL;
    const int t2 = t1 + CHL;
    int t0 = t1 - LEADL; if (t0 < 0) t0 = 0;

    unsigned long long hh[10];
    #pragma unroll
    for (int m = 0; m < 10; m++) hh[m] = 0ull;
    float c = 0.f;
    const float* xp = g_xproj;
    float A[4], B[4];

#define LOAD4(S, t) { const float* p = xp + (size_t)(t) * 40 + k; \
    S[0] = p[0]; S[1] = p[10]; S[2] = p[20]; S[3] = p[30]; }

#define STEP(S, tc) { int tp = (tc) + 2; if (tp > NSTEP - 1) tp = NSTEP - 1; \
    unsigned long long aif = pk2(S[0], S[1]), ago = pk2(S[2], S[3]); \
    LOAD4(S, tp); \
    _Pragma("unroll") \
    for (int m = 0; m < 10; m++) { \
        aif = fma2(wif[m], hh[m], aif); ago = fma2(wgo[m], hh[m], ago); } \
    float ai, af, ag, ao; upk2(aif, ai, af); upk2(ago, ag, ao); \
    float tg = tfast(ag); \
    c = fmaf(sigf(af), c, sigf(ai) * tg); \
    float hk = sigf(ao) * tfast(c); \
    if (lane < 10 && (tc) >= t1) g_hseq[(size_t)(tc) * 10 + lane] = hk; \
    _Pragma("unroll") \
    for (int m = 0; m < 10; m++) { \
        float hm = __shfl_sync(0xffffffffu, hk, m); hh[m] = pk2(hm, hm); } }

    LOAD4(A, t0); LOAD4(B, t0 + 1);
    for (int t = t0; t < t2; t += 2) {
        STEP(A, t);
        STEP(B, t + 1);
    }
#undef STEP
#undef LOAD4
}

// ---------------- fc+skip inner body ----------------
template <int FOUT>
__device__ __forceinline__ void fcskip_row(const float* __restrict__ s4row,
                                           const float* __restrict__ xrow,
                                           const float* __restrict__ wfc,
                                           const float* __restrict__ wsk,
                                           const float* __restrict__ bb,
                                           float* __restrict__ orow) {
    float acc[FOUT];
    #pragma unroll
    for (int o = 0; o < FOUT; o++) acc[o] = bb[o];
    #pragma unroll
    for (int m = 0; m < 20; m++) {
        float sm = s4row[m], xm = xrow[m];
        #pragma unroll
        for (int o = 0; o < FOUT; o++)
            acc[o] = fmaf(sm, wfc[o * 20 + m], fmaf(xm, wsk[o * 20 + m], acc[o]));
    }
    #pragma unroll
    for (int o = 0; o < FOUT; o++) orow[o] = acc[o];
}

// ---------------- K3: fused HR module (templated; segmented in-block LIF chains;
//                   lif4 writes to a SEPARATE buffer -> no cross-segment race) ----
template <int WHICH>
__global__ void __launch_bounds__(256, 2)
k_hr(const float* __restrict__ scw, const float* __restrict__ scb,
     const float* __restrict__ cw,  const float* __restrict__ cb,
     const float* __restrict__ fw,  const float* __restrict__ fb,
     const float* __restrict__ skw, const float* __restrict__ skb) {
    extern __shared__ float sm[];
    float* sx  = sm;                 // [RMAX][20] xin
    float* shl = sm + RMAX * 20;     // [RMAX][60] lif3 spikes
    float* sc4 = sm + RMAX * 80;     // [RMAX][20] staging / conv out
    float* ss4 = sm + RMAX * 100;    // [RMAX][20] lif4 spikes (separate: race-free)

    constexpr int FOUT = WHICH ? 10 : 20;
    __shared__ float w_cv[1200], w_fc[FOUT * 20], w_sk[FOUT * 20], w_sc[200];
    __shared__ float b_cv[20], b_fs[FOUT], b_sc[20];

    const int tid = threadIdx.x;
    for (int i = tid; i < 1200; i += 256) w_cv[i] = cw[i];
    for (int i = tid; i < FOUT * 20; i += 256) { w_fc[i] = fw[i]; w_sk[i] = skw[i]; }
    if (WHICH == 0) for (int i = tid; i < 200; i += 256) w_sc[i] = scw[i];
    if (tid < 20) { b_cv[tid] = cb[tid]; if (WHICH == 0) b_sc[tid] = scb[tid]; }
    if (tid < FOUT) b_fs[tid] = fb[tid] + skb[tid];

    const int t1 = blockIdx.x * CHK;
    int t0 = t1 - 64; if (t0 < 0) t0 = 0;
    const int R = t1 + CHK - t0;
    const int rconv = (t1 >= 32 ? t1 - 32 : 0) - t0;   // 32 (or 0 for block 0)
    const int rkeep = t1 - t0;                         // 64 (or 0 for block 0)

    // ---- stage A: xin into sx ----
    if (WHICH == 0) {
        // stage hseq chunk into sc4 (coalesced float4), then small matmul from smem
        {
            const float4* h4 = (const float4*)(g_hseq + (size_t)t0 * 10);
            float4* d4 = (float4*)sc4;
            const int n4 = (R * 10) >> 2;
            for (int i = tid; i < n4; i += 256) d4[i] = h4[i];
        }
        __syncthreads();
        for (int i = tid; i < R * 20; i += 256) {
            int r = i / 20, o = i % 20;
            float acc = b_sc[o];
            const float* hr = sc4 + r * 10;
            #pragma unroll
            for (int m = 0; m < 10; m++) acc = fmaf(hr[m], w_sc[o * 10 + m], acc);
            sx[i] = acc;
        }
    } else {
        const float4* s4p = (const float4*)(g_out1 + (size_t)t0 * 20);
        float4* d4 = (float4*)sx;
        const int n4 = (R * 20) >> 2;
        for (int i = tid; i < n4; i += 256) d4[i] = s4p[i];
    }
    __syncthreads();

    // ---- stage B: lif3, 4 time-segments x 60 chains (240 threads, depth <= 72) ----
    // reads sx (never written here), writes shl -> no cross-segment hazard.
    if (tid < 240) {
        const int seg = tid / 60;
        const int l = tid % 60;
        const int kk = l / 20, f = l % 20;
        float tau = (kk == 0) ? 1.2231301601484298f
                  : (kk == 1) ? 1.3678794411714423f : 1.4493289641172216f;
        float th  = (kk == 0) ? 0.14f : (kk == 1) ? 0.08f : 0.06f;
        float invt = 1.0f / tau, om = 1.0f - invt;
        const int OW = R - rconv;            // 160 (block 0: 128), divisible by 4
        const int ws = OW >> 2;              // 40 (block 0: 32)
        const int k1 = rconv + seg * ws;
        const int k2 = k1 + ws;
        int cs = k1 - 32; if (cs < 0) cs = 0;
        float v = 0.f;
        float* op = shl + f * 3 + kk;
        const float* ip = sx + f;
        #pragma unroll 2
        for (int r = cs; r < k2; r++) {
            float d = fmaf(v, om, fmaf(ip[r * 20], invt, -th));
            int msk = __float_as_int(d) >> 31;
            if (r >= k1) op[r * 60] = __int_as_float(~msk & 0x3f800000);
            v = __int_as_float(__float_as_int(d + th) & msk);
        }
    }
    __syncthreads();

    // ---- stage C: conv (rows [rconv,R)); warp-uniform output half (wv broadcast) ----
    {
        const int nrows = R - rconv;          // 160, or 128 for block 0 (mult of 32)
        const int ntask = nrows * 2;
        for (int task = tid; task < ntask; task += 256) {
            int r, ob;
            if (task < nrows) { r = rconv + task;         ob = 0;  }
            else              { r = rconv + task - nrows; ob = 10; }
            float acc[10];
            #pragma unroll
            for (int o = 0; o < 10; o++) acc[o] = b_cv[ob + o];
            const float4* hrow = (const float4*)(shl + r * 60);
            #pragma unroll
            for (int mb = 0; mb < 15; mb++) {
                float4 hv = hrow[mb];
                #pragma unroll
                for (int o = 0; o < 10; o++) {
                    const float4 wv = *(const float4*)(w_cv + (ob + o) * 60 + mb * 4);
                    acc[o] = fmaf(hv.x, wv.x, acc[o]);
                    acc[o] = fmaf(hv.y, wv.y, acc[o]);
                    acc[o] = fmaf(hv.z, wv.z, acc[o]);
                    acc[o] = fmaf(hv.w, wv.w, acc[o]);
                }
            }
            #pragma unroll
            for (int o = 0; o < 10; o++) sc4[r * 20 + ob + o] = acc[o];
        }
    }
    __syncthreads();

    // ---- stage D: lif4, 8 time-segments x 20 chains (160 threads, depth <= 48) ----
    // reads sc4 (conv out, never written here), writes ss4 -> race-free.
    if (tid < 160) {
        const int seg = tid / 20;
        const int f = tid % 20;
        const float invt = 1.0f / 1.3678794411714423f;
        const float om = 1.0f - invt, th = 0.08f;
        const int OW = R - rkeep;            // 128 always, divisible by 8
        const int ws = OW >> 3;              // 16
        const int k1 = rkeep + seg * ws;
        const int k2 = k1 + ws;
        int cs = k1 - 32; if (cs < rconv) cs = rconv;
        float v = 0.f;
        const float* ip = sc4 + f;
        float* op = ss4 + f;
        #pragma unroll 2
        for (int r = cs; r < k2; r++) {
            float d = fmaf(v, om, fmaf(ip[r * 20], invt, -th));
            int msk = __float_as_int(d) >> 31;
            if (r >= k1) op[r * 20] = __int_as_float(~msk & 0x3f800000);
            v = __int_as_float(__float_as_int(d + th) & msk);
        }
    }
    __syncthreads();

    // ---- stage E: fc + skip on keep rows ----
    {
        int r = rkeep + tid;
        if (r < R) {
            if (WHICH == 0)
                fcskip_row<20>(ss4 + r * 20, sx + r * 20, w_fc, w_sk, b_fs,
                               g_out1 + (size_t)(t0 + r) * 20);
            else
                fcskip_row<10>(ss4 + r * 20, sx + r * 20, w_fc, w_sk, b_fs,
                               g_out2 + (size_t)(t0 + r) * 10);
        }
    }
}

// ---------------- K4: final LIF over batch axis, chunked + 16-deep prefetch ring ----
__global__ void k_liff() {
    int idx = threadIdx.x;
    if (idx >= 1000) return;
    const float invt = 1.0f / 1.3678794411714423f;
    const float om = 1.0f - invt, th = 0.08f;
    const int b1 = blockIdx.x * 32, b2 = b1 + 32;
    int b0 = b1 - 48; if (b0 < 0) b0 = 0;
    const int n = b2 - b0;                 // 80, or 32 for block 0 (both mult of 16)
    const int wskip = b1 - b0;
    const float* ip = g_out2 + (size_t)b0 * 1000 + idx;
    float* op = g_sfin + (size_t)b0 * 1000 + idx;

    float v = 0.f;
    float xr[16];
    #pragma unroll
    for (int u = 0; u < 16; u++) xr[u] = fmaf(ip[(size_t)u * 1000], invt, -th);
    for (int bb = 0; bb < n; bb += 16) {
        #pragma unroll
        for (int u = 0; u < 16; u++) {
            int t = bb + u;
            float d = fmaf(v, om, xr[u]);
            int np = t + 16;
            float nx = (np < n) ? ip[(size_t)np * 1000] : 0.f;
            xr[u] = fmaf(nx, invt, -th);
            int msk = __float_as_int(d) >> 31;
            if (t >= wskip) op[(size_t)t * 1000] = __int_as_float(~msk & 0x3f800000);
            v = __int_as_float(__float_as_int(d + th) & msk);
        }
    }
}

// ---------------- K5: dp / avg / fused + per-batch partial sums ----------------
__global__ void k_fused() {
    int b = blockIdx.x, m = threadIdx.x;
    float dp[10];
    float s1 = 0.f, s2 = 0.f;
    if (m < 20) {
        const float* sb = g_sfin + b * 1000;
        float avgm = 0.f;
        #pragma unroll
        for (int j = 0; j < 10; j++) {
            float a = sb[(5 * m + 3) * 10 + j] + sb[(5 * m + 4) * 10 + j]
                    - sb[(5 * m + 0) * 10 + j] - sb[(5 * m + 1) * 10 + j];
            dp[j] = 0.5f * a;
            avgm += dp[j];
        }
        avgm *= 0.1f;
        #pragma unroll
        for (int j = 0; j < 10; j++) {
            float fv = dp[j] * avgm;
            g_fused[b * 200 + j * 20 + m] = fv;
            s1 += fv; s2 += fv * fv;
        }
    }
    #pragma unroll
    for (int off = 16; off; off >>= 1) {
        s1 += __shfl_xor_sync(0xffffffffu, s1, off);
        s2 += __shfl_xor_sync(0xffffffffu, s2, off);
    }
    if (m == 0) { g_part[b * 2] = s1; g_part[b * 2 + 1] = s2; }
}

// ---------------- K6: global mean/var ----------------
__global__ void k_stats(const float* __restrict__ gamma, const float* __restrict__ beta) {
    int l = threadIdx.x;
    float s1 = 0.f, s2 = 0.f;
    for (int i = l; i < BATCH; i += 32) { s1 += g_part[2 * i]; s2 += g_part[2 * i + 1]; }
    #pragma unroll
    for (int off = 16; off; off >>= 1) {
        s1 += __shfl_xor_sync(0xffffffffu, s1, off);
        s2 += __shfl_xor_sync(0xffffffffu, s2, off);
    }
    if (l == 0) {
        float n = (float)(BATCH * 200);
        float mean = s1 / n;
        float var = s2 / n - mean * mean;
        float rstd = 1.f / sqrtf(var + 1e-5f);
        g_stats[0] = mean; g_stats[1] = rstd * gamma[0]; g_stats[2] = beta[0];
    }
}

// ---------------- K7: BN + classifier + log_softmax ----------------
__global__ void k_logits(const float* __restrict__ clsw, const float* __restrict__ clsb,
                         float* __restrict__ out) {
    int b = blockIdx.x, l = threadIdx.x;
    float mean = g_stats[0], ga = g_stats[1], be = g_stats[2];
    float a0 = 0.f, a1 = 0.f, a2 = 0.f;
    for (int n = l; n < 200; n += 32) {
        float bn = (g_fused[b * 200 + n] - mean) * ga + be;
        a0 = fmaf(bn, clsw[n], a0);
        a1 = fmaf(bn, clsw[200 + n], a1);
        a2 = fmaf(bn, clsw[400 + n], a2);
    }
    #pragma unroll
    for (int off = 16; off; off >>= 1) {
        a0 += __shfl_xor_sync(0xffffffffu, a0, off);
        a1 += __shfl_xor_sync(0xffffffffu, a1, off);
        a2 += __shfl_xor_sync(0xffffffffu, a2, off);
    }
    if (l == 0) {
        float l0 = a0 + clsb[0], l1 = a1 + clsb[1], l2 = a2 + clsb[2];
        float mx = fmaxf(l0, fmaxf(l1, l2));
        float e0 = expf(l0 - mx), e1 = expf(l1 - mx), e2 = expf(l2 - mx);
        float lse = logf(e0 + e1 + e2) + mx;
        out[b * 3 + 0] = l0 - lse;
        out[b * 3 + 1] = l1 - lse;
        out[b * 3 + 2] = l2 - lse;
    }
}

// ---------------- launch ----------------
extern "C" void kernel_launch(void* const* d_in, const int* in_sizes, int n_in,
                              void* d_out, int out_size) {
    const float* x   = (const float*)d_in[0];
    const float* wih = (const float*)d_in[1];
    const float* whh = (const float*)d_in[2];
    const float* bih = (const float*)d_in[3];
    const float* bhh = (const float*)d_in[4];
    const float* scw = (const float*)d_in[5];
    const float* scb = (const float*)d_in[6];
    const float* c1w = (const float*)d_in[7];
    const float* c1b = (const float*)d_in[8];
    const float* f1w = (const float*)d_in[9];
    const float* f1b = (const float*)d_in[10];
    const float* s1w = (const float*)d_in[11];
    const float* s1b = (const float*)d_in[12];
    const float* c2w = (const float*)d_in[13];
    const float* c2b = (const float*)d_in[14];
    const float* f2w = (const float*)d_in[15];
    const float* f2b = (const float*)d_in[16];
    const float* s2w = (const float*)d_in[17];
    const float* s2b = (const float*)d_in[18];
    const float* gam = (const float*)d_in[19];
    const float* bet = (const float*)d_in[20];
    const float* clw = (const float*)d_in[21];
    const float* clb = (const float*)d_in[22];
    float* out = (float*)d_out;

    static int smem_set = 0;
    const int HR_SMEM = RMAX * 120 * sizeof(float);   // 92.2 KB
    if (!smem_set) {
        cudaFuncSetAttribute(k_hr<0>, cudaFuncAttributeMaxDynamicSharedMemorySize, HR_SMEM);
        cudaFuncSetAttribute(k_hr<1>, cudaFuncAttributeMaxDynamicSharedMemorySize, HR_SMEM);
        smem_set = 1;
    }

    k_xproj <<<512, 256>>>(x, wih, bih, bhh);
    k_lstm  <<<NCHL, 32>>>(whh);
    k_hr<0> <<<NCHK, 256, HR_SMEM>>>(scw, scb, c1w, c1b, f1w, f1b, s1w, s1b);
    k_hr<1> <<<NCHK, 256, HR_SMEM>>>(scw, scb, c2w, c2b, f2w, f2b, s2w, s2b);
    k_liff  <<<16, 1024>>>();
    k_fused <<<512, 32>>>();
    k_stats <<<1, 32>>>(gam, bet);
    k_logits<<<512, 32>>>(clw, clb, out);
}